// round 5
// baseline (speedup 1.0000x reference)
#include <cuda_runtime.h>

#define NB 8
#define NS 2048
#define ND 20
#define NH 4
#define NDK 5
#define FULLM 0xffffffffu

__device__ __forceinline__ float ex2f(float x) {
    float r; asm("ex2.approx.ftz.f32 %0, %1;" : "=f"(r) : "f"(x)); return r;
}
__device__ __forceinline__ float tf32r(float x) {
    unsigned u; asm("cvt.rna.tf32.f32 %0, %1;" : "=r"(u) : "f"(x));
    return __uint_as_float(u);
}
// exp2 via magic-constant range reduction + degree-4 Taylor (fma pipe).
// |rel err| ~6e-5 on r in [-0.5,0.5]; valid for |x| < 250 (scores are << this).
__device__ __forceinline__ float exp2poly(float x) {
    float t = __fadd_rn(x, 12582912.0f);           // round(x) in low mantissa
    int i = __float_as_int(t) << 23;               // = n<<23 (two's-complement wrap)
    float r = __fsub_rn(x, __fsub_rn(t, 12582912.0f));
    float p = fmaf(r, 0.0096181291f, 0.0555041087f);
    p = fmaf(p, r, 0.2402265069f);
    p = fmaf(p, r, 0.6931471806f);
    p = fmaf(p, r, 1.0f);
    return __int_as_float(__float_as_int(p) + i);
}

// Scratch (device globals)
__device__ int   g_cidx[NB][NS];
__device__ int   g_nk[NB];
// Fragment storage (every read slot is written every run — no memset needed):
// Qf: A-frag planes a0,a1 (dims 0..3); Q4: dim-4 per query row (sparse plane a2/a3
//     reconstructed in attn via predicated select).
// Kf: B-frag plane b0 (dims 0..3); K4: dim-4 per key (sparse plane b1 likewise).
// Vf: B-frag planes of PV mma; key rows permuted M=[0,2,4,6,1,3,5,7] so the
//     EX2'd score C-frag feeds the PV A-frag with no shuffles. n=5 = ones col,
//     n=6,7 zero cols (written by proj); pad keys zeroed by compact_kernel.
__device__ float g_Qf[3][NB][NH][128][2][32];
__device__ float g_Q4[3][NB][NH][128][16];
__device__ float g_Kf[3][NB][NH][256][32];
__device__ float g_K4[3][NB][NH][256][8];
__device__ float g_Vf[3][NB][NH][256][2][32];
__device__ float g_O[NB][NS][ND];   // summed over all 6 pairs

// ---------------------------------------------------------------------------
// 1) Per-batch key compaction + zero-fill of pad key slots in the last chunk
// ---------------------------------------------------------------------------
__global__ void compact_kernel(const int* __restrict__ mask) {
    int b = blockIdx.x;
    int lane = threadIdx.x;
    int count = 0;
    for (int s0 = 0; s0 < NS; s0 += 32) {
        int m = mask[b * NS + s0 + lane];
        unsigned bal = __ballot_sync(FULLM, m != 0);
        int pos = count + __popc(bal & ((1u << lane) - 1u));
        g_cidx[b][s0 + lane] = m ? pos : -1;
        count += __popc(bal);
    }
    if (lane == 0) g_nk[b] = count;

    int nk = count;                      // same in all lanes
    int npad = (8 - (nk & 7)) & 7;
    if (npad) {
        for (int u = lane; u < 12 * npad; u += 32) {
            int pp  = u % npad;
            int sh  = u / npad;
            int src = sh >> 2, h = sh & 3;
            int j = nk + pp;
            int ch = j >> 3, w = j & 7, vp = w & 1, vr = w >> 1;
            float* Kp = &g_Kf[src][b][h][ch][0];
            Kp[w * 4 + 0] = 0.f; Kp[w * 4 + 1] = 0.f;
            Kp[w * 4 + 2] = 0.f; Kp[w * 4 + 3] = 0.f;
            g_K4[src][b][h][ch][w] = 0.f;
            float* Vp = &g_Vf[src][b][h][ch][vp][0];
#pragma unroll
            for (int d = 0; d < 8; d++) Vp[d * 4 + vr] = 0.f;
        }
    }
}

// ---------------------------------------------------------------------------
// 2) Projections: thread = (src, h, bs) -> 5 outputs x 3 matrices
// ---------------------------------------------------------------------------
__global__ void proj_kernel(const float* __restrict__ xq,
                            const float* __restrict__ xk,
                            const float* __restrict__ xv,
                            const float* __restrict__ W0, const float* __restrict__ b0,
                            const float* __restrict__ W1, const float* __restrict__ b1,
                            const float* __restrict__ W2, const float* __restrict__ b2) {
    __shared__ float sW[3][ND * ND];
    __shared__ float sb[3][ND];
    for (int i = threadIdx.x; i < ND * ND; i += blockDim.x) {
        sW[0][i] = W0[i]; sW[1][i] = W1[i]; sW[2][i] = W2[i];
    }
    for (int i = threadIdx.x; i < ND; i += blockDim.x) {
        sb[0][i] = b0[i]; sb[1][i] = b1[i]; sb[2][i] = b2[i];
    }
    __syncthreads();

    int idx = blockIdx.x * blockDim.x + threadIdx.x;
    if (idx >= 3 * NH * NB * NS) return;
    int bs  = idx & (NB * NS - 1);
    int sh  = idx >> 14;                 // NB*NS = 16384 = 2^14
    int src = sh >> 2, h = sh & 3;
    int b   = bs / NS;
    int s   = bs - b * NS;

    const float* x = (src == 0 ? xq : (src == 1 ? xk : xv)) + (size_t)bs * ND;
    float xr[ND];
#pragma unroll
    for (int i = 0; i < ND; i++) xr[i] = x[i];

    int cj = g_cidx[b][s];
    int qt = s >> 4, r = s & 15;
    int qg = r & 7, half = r >> 3;
    int ch = cj >> 3;
    int w  = cj & 7;
    int vplane = w & 1, vr = w >> 1;
    const float qsc = 1.44269504088896340736f * 0.44721359549995793928f;

#pragma unroll
    for (int d = 0; d < NDK; d++) {
        int o = h * NDK + d;
        float y0 = sb[0][o], y1 = sb[1][o], y2 = sb[2][o];
#pragma unroll
        for (int i = 0; i < ND; i++) {
            y0 = fmaf(xr[i], sW[0][o * ND + i], y0);
            y1 = fmaf(xr[i], sW[1][o * ND + i], y1);
            y2 = fmaf(xr[i], sW[2][o * ND + i], y2);
        }
        y0 = tf32r(y0 * qsc);
        y1 = tf32r(y1);
        y2 = tf32r(y2);
        if (d < 4) g_Qf[src][b][h][qt][half][qg * 4 + d] = y0;
        else       g_Q4[src][b][h][qt][r] = y0;
        if (cj >= 0) {
            if (d < 4) g_Kf[src][b][h][ch][w * 4 + d] = y1;
            else       g_K4[src][b][h][ch][w] = y1;
            g_Vf[src][b][h][ch][vplane][d * 4 + vr] = y2;
            if (d == 4) {   // ones col (n=5) + zero cols (n=6,7)
                g_Vf[src][b][h][ch][vplane][20 + vr] = 1.0f;
                g_Vf[src][b][h][ch][vplane][24 + vr] = 0.0f;
                g_Vf[src][b][h][ch][vplane][28 + vr] = 0.0f;
            }
        }
    }
}

// ---------------------------------------------------------------------------
// 3) Attention: warp = (b,h,16q); all 6 pairs fused; hybrid MUFU/poly exp.
// ---------------------------------------------------------------------------
#define SMMA(s0, s1, s2, s3, A, B0, B1)                                      \
    asm volatile(                                                            \
        "mma.sync.aligned.m16n8k8.row.col.f32.tf32.tf32.f32 "                \
        "{%0,%1,%2,%3}, {%4,%5,%6,%7}, {%8,%9}, {%10,%10,%10,%10};\n"        \
        : "=f"(s0), "=f"(s1), "=f"(s2), "=f"(s3)                             \
        : "r"(A[0]), "r"(A[1]), "r"(A[2]), "r"(A[3]),                        \
          "r"(B0), "r"(B1), "f"(0.f))

#define PVMMA(O, e0, e1, e2, e3, B0, B1)                                     \
    asm volatile(                                                            \
        "mma.sync.aligned.m16n8k8.row.col.f32.tf32.tf32.f32 "                \
        "{%0,%1,%2,%3}, {%4,%5,%6,%7}, {%8,%9}, {%0,%1,%2,%3};\n"            \
        : "+f"(O[0]), "+f"(O[1]), "+f"(O[2]), "+f"(O[3])                     \
        : "r"(__float_as_uint(e0)), "r"(__float_as_uint(e2)),                \
          "r"(__float_as_uint(e1)), "r"(__float_as_uint(e3)),                \
          "r"(B0), "r"(B1))

#define EXPSEL(s, USEM) ((USEM) ? ex2f(s) : exp2poly(s))

#define DO_PAIR(P, A, M0, M1, M2, M3)                                        \
    {                                                                        \
        float s0, s1, s2, s3;                                                \
        SMMA(s0, s1, s2, s3, ua[A], kb0, kb1);                               \
        float e0 = EXPSEL(s0, M0), e1 = EXPSEL(s1, M1);                      \
        float e2 = EXPSEL(s2, M2), e3 = EXPSEL(s3, M3);                      \
        PVMMA(o[P], e0, e1, e2, e3, vb0, vb1);                               \
    }

__global__ void __launch_bounds__(128) attn_kernel() {
    int bi  = blockIdx.x;                 // [NB][NH][32]
    int b   = bi >> 7;
    int h   = (bi >> 5) & 3;
    int qt4 = bi & 31;
    int wid  = threadIdx.x >> 5;
    int lane = threadIdx.x & 31;
    int qt   = qt4 * 4 + wid;
    int nc = (g_nk[b] + 7) >> 3;
    int t = lane & 3;
    int g = lane >> 2;
    bool t0 = (t == 0);

    unsigned ua[3][4];
#pragma unroll
    for (int a = 0; a < 3; a++) {
        const float* Qb = &g_Qf[a][b][h][qt][0][0];
        ua[a][0] = __float_as_uint(Qb[lane]);
        ua[a][1] = __float_as_uint(Qb[32 + lane]);
        float qlo = g_Q4[a][b][h][qt][g];
        float qhi = g_Q4[a][b][h][qt][8 + g];
        ua[a][2] = t0 ? __float_as_uint(qlo) : 0u;
        ua[a][3] = t0 ? __float_as_uint(qhi) : 0u;
    }
    const float* K0 = &g_Kf[0][b][h][0][0];
    const float* K1 = &g_Kf[1][b][h][0][0];
    const float* K2 = &g_Kf[2][b][h][0][0];
    const float* Kq0 = &g_K4[0][b][h][0][0];
    const float* Kq1 = &g_K4[1][b][h][0][0];
    const float* Kq2 = &g_K4[2][b][h][0][0];
    const float* V0 = &g_Vf[0][b][h][0][0][0];
    const float* V1 = &g_Vf[1][b][h][0][0][0];
    const float* V2 = &g_Vf[2][b][h][0][0][0];

    float o[6][4];
#pragma unroll
    for (int p = 0; p < 6; p++)
#pragma unroll
        for (int i = 0; i < 4; i++) o[p][i] = 0.f;

    for (int ch = 0; ch < nc; ch++) {
        int o32 = ch * 32 + lane;
        int o64 = ch * 64 + lane;
        int o8  = ch * 8 + g;
        {   // kv-src 0 : pairs 1 (a=1), 3 (a=2)
            unsigned kb0 = __float_as_uint(K0[o32]);
            unsigned kb1 = t0 ? __float_as_uint(Kq0[o8]) : 0u;
            unsigned vb0 = __float_as_uint(V0[o64]);
            unsigned vb1 = __float_as_uint(V0[o64 + 32]);
            DO_PAIR(1, 1, true, true, true, true);
            DO_PAIR(3, 2, true, true, true, false);
        }
        {   // kv-src 1 : pairs 0 (a=0), 5 (a=2)
            unsigned kb0 = __float_as_uint(K1[o32]);
            unsigned kb1 = t0 ? __float_as_uint(Kq1[o8]) : 0u;
            unsigned vb0 = __float_as_uint(V1[o64]);
            unsigned vb1 = __float_as_uint(V1[o64 + 32]);
            DO_PAIR(0, 0, true, true, true, true);
            DO_PAIR(5, 2, false, false, false, false);
        }
        {   // kv-src 2 : pairs 2 (a=0), 4 (a=1)
            unsigned kb0 = __float_as_uint(K2[o32]);
            unsigned kb1 = t0 ? __float_as_uint(Kq2[o8]) : 0u;
            unsigned vb0 = __float_as_uint(V2[o64]);
            unsigned vb1 = __float_as_uint(V2[o64 + 32]);
            DO_PAIR(2, 0, true, true, true, true);
            DO_PAIR(4, 1, false, false, false, false);
        }
    }

    // Normalize each pair (l = col 5 -> regs 1/3 of lane group t=2), sum pairs.
    unsigned lsrc = (lane & ~3u) | 2u;
    float r0 = 0.f, r1 = 0.f, r2 = 0.f, r3 = 0.f;
#pragma unroll
    for (int p = 0; p < 6; p++) {
        float llo = __shfl_sync(FULLM, o[p][1], lsrc);
        float lhi = __shfl_sync(FULLM, o[p][3], lsrc);
        float ilo = 1.0f / llo;
        float ihi = 1.0f / lhi;
        r0 = fmaf(o[p][0], ilo, r0);
        r1 = fmaf(o[p][1], ilo, r1);
        r2 = fmaf(o[p][2], ihi, r2);
        r3 = fmaf(o[p][3], ihi, r3);
    }

    int q_lo = qt * 16 + g;
    int q_hi = q_lo + 8;
    int c0 = 2 * t;
    if (c0 < 4) {
        g_O[b][q_lo][h * NDK + c0]     = r0;
        g_O[b][q_lo][h * NDK + c0 + 1] = r1;
        g_O[b][q_hi][h * NDK + c0]     = r2;
        g_O[b][q_hi][h * NDK + c0 + 1] = r3;
    } else if (c0 == 4) {
        g_O[b][q_lo][h * NDK + 4] = r0;
        g_O[b][q_hi][h * NDK + 4] = r2;
    }
}

// ---------------------------------------------------------------------------
// 4) Output projection: thread = (bs, og) -> 5 outputs
// ---------------------------------------------------------------------------
__global__ void outproj_kernel(const float* __restrict__ W3,
                               const float* __restrict__ b3,
                               float* __restrict__ out) {
    __shared__ float sW[ND * ND];
    __shared__ float sb[ND];
    for (int i = threadIdx.x; i < ND * ND; i += blockDim.x) sW[i] = W3[i];
    for (int i = threadIdx.x; i < ND; i += blockDim.x) sb[i] = b3[i];
    __syncthreads();

    int idx = blockIdx.x * blockDim.x + threadIdx.x;
    if (idx >= 4 * NB * NS) return;
    int bs = idx & (NB * NS - 1);
    int og = idx >> 14;

    const float* xp = &g_O[0][0][0] + (size_t)bs * ND;
    float x[ND];
#pragma unroll
    for (int i = 0; i < ND; i++) x[i] = xp[i];
    float* op = out + (size_t)bs * ND;
#pragma unroll
    for (int d = 0; d < 5; d++) {
        int o = og * 5 + d;
        float y = sb[o];
#pragma unroll
        for (int i = 0; i < ND; i++) y = fmaf(x[i], sW[o * ND + i], y);
        op[o] = y;
    }
}

// ---------------------------------------------------------------------------
extern "C" void kernel_launch(void* const* d_in, const int* in_sizes, int n_in,
                              void* d_out, int out_size) {
    const float* q   = (const float*)d_in[0];
    const float* k   = (const float*)d_in[1];
    const float* v   = (const float*)d_in[2];
    const int*   msk = (const int*)d_in[3];
    const float* W0  = (const float*)d_in[4];
    const float* b0  = (const float*)d_in[5];
    const float* W1  = (const float*)d_in[6];
    const float* b1  = (const float*)d_in[7];
    const float* W2  = (const float*)d_in[8];
    const float* b2  = (const float*)d_in[9];
    const float* W3  = (const float*)d_in[10];
    const float* b3  = (const float*)d_in[11];
    float* out = (float*)d_out;

    compact_kernel<<<NB, 32>>>(msk);
    proj_kernel<<<(3 * NH * NB * NS + 255) / 256, 256>>>(q, k, v, W0, b0, W1, b1, W2, b2);
    attn_kernel<<<NB * NH * 32, 128>>>();
    outproj_kernel<<<(4 * NB * NS + 255) / 256, 256>>>(W3, b3, out);
}

// round 6
// speedup vs baseline: 1.4069x; 1.4069x over previous
#include <cuda_runtime.h>

#define NB 8
#define NS 2048
#define ND 20
#define NH 4
#define NDK 5
#define FULLM 0xffffffffu

__device__ __forceinline__ float ex2f(float x) {
    float r; asm("ex2.approx.ftz.f32 %0, %1;" : "=f"(r) : "f"(x)); return r;
}
__device__ __forceinline__ float tf32r(float x) {
    unsigned u; asm("cvt.rna.tf32.f32 %0, %1;" : "=r"(u) : "f"(x));
    return __uint_as_float(u);
}

// Scratch (device globals). Interleaved fragment layouts (vector loads):
// Qf[qt][lane][0..3] = A-frag planes a0..a3 of the QK mma (one float4 per lane).
//   a0/a1: dims 0..3 for query halves; a2/a3: sparse dim-4 plane (t==0 lanes
//   hold q[4], t=1..3 lanes written 0 by proj).
// Kf[ch][lane][0..1] = B-frag planes b0,b1 (float2 per lane). b1 sparse likewise.
// Vf[ch][lane][0..1] = B-frag planes of the PV mma; key rows permuted by
//   M=[0,2,4,6,1,3,5,7] so the EX2'd score C-frag feeds the PV A-frag with no
//   shuffles. Col n=5 is the ones column (row-sum l), n=6,7 zero columns.
// Every read slot is written every run (proj/compact) -> no memset kernels.
__device__ float g_Qf[3][NB][NH][128][32][4];
__device__ float g_Kf[3][NB][NH][256][32][2];
__device__ float g_Vf[3][NB][NH][256][32][2];
__device__ int   g_cidx[NB][NS];
__device__ int   g_nk[NB];
__device__ float g_O[NB][NS][ND];   // attention output summed over all 6 pairs

// ---------------------------------------------------------------------------
// 1) Per-batch key compaction + zero-fill of pad key slots in the last chunk
// ---------------------------------------------------------------------------
__global__ void compact_kernel(const int* __restrict__ mask) {
    int b = blockIdx.x;
    int lane = threadIdx.x;
    int count = 0;
    for (int s0 = 0; s0 < NS; s0 += 32) {
        int m = mask[b * NS + s0 + lane];
        unsigned bal = __ballot_sync(FULLM, m != 0);
        int pos = count + __popc(bal & ((1u << lane) - 1u));
        g_cidx[b][s0 + lane] = m ? pos : -1;
        count += __popc(bal);
    }
    if (lane == 0) g_nk[b] = count;

    int nk = count;                      // identical in all lanes
    int npad = (8 - (nk & 7)) & 7;
    if (npad) {
        for (int u = lane; u < 12 * npad; u += 32) {
            int pp  = u % npad;
            int sh  = u / npad;
            int src = sh >> 2, h = sh & 3;
            int j = nk + pp;
            int ch = j >> 3, w = j & 7, vp = w & 1, vr = w >> 1;
#pragma unroll
            for (int i = 0; i < 4; i++) {
                g_Kf[src][b][h][ch][w * 4 + i][0] = 0.f;
                g_Kf[src][b][h][ch][w * 4 + i][1] = 0.f;
            }
#pragma unroll
            for (int d = 0; d < 8; d++)
                g_Vf[src][b][h][ch][d * 4 + vr][vp] = 0.f;
        }
    }
}

// ---------------------------------------------------------------------------
// 2) Projections: thread = (src, h, bs) -> 5 dims x 3 matrices
// ---------------------------------------------------------------------------
__global__ void proj_kernel(const float* __restrict__ xq,
                            const float* __restrict__ xk,
                            const float* __restrict__ xv,
                            const float* __restrict__ W0, const float* __restrict__ b0,
                            const float* __restrict__ W1, const float* __restrict__ b1,
                            const float* __restrict__ W2, const float* __restrict__ b2) {
    __shared__ float sW[3][ND * ND];
    __shared__ float sb[3][ND];
    for (int i = threadIdx.x; i < ND * ND; i += blockDim.x) {
        sW[0][i] = W0[i]; sW[1][i] = W1[i]; sW[2][i] = W2[i];
    }
    for (int i = threadIdx.x; i < ND; i += blockDim.x) {
        sb[0][i] = b0[i]; sb[1][i] = b1[i]; sb[2][i] = b2[i];
    }
    __syncthreads();

    int idx = blockIdx.x * blockDim.x + threadIdx.x;
    if (idx >= 3 * NH * NB * NS) return;
    int bs  = idx & (NB * NS - 1);
    int sh  = idx >> 14;                 // NB*NS = 16384 = 2^14
    int src = sh >> 2, h = sh & 3;
    int b   = bs / NS;
    int s   = bs - b * NS;

    const float* x = (src == 0 ? xq : (src == 1 ? xk : xv)) + (size_t)bs * ND;
    float xr[ND];
#pragma unroll
    for (int i = 0; i < ND; i++) xr[i] = x[i];

    int cj = g_cidx[b][s];
    int qt = s >> 4, r = s & 15;
    int qg = r & 7, half = r >> 3;
    int ch = cj >> 3;
    int w  = cj & 7;
    int vp = w & 1, vr = w >> 1;
    const float qsc = 1.44269504088896340736f * 0.44721359549995793928f;

#pragma unroll
    for (int d = 0; d < NDK; d++) {
        int o = h * NDK + d;
        float y0 = sb[0][o], y1 = sb[1][o], y2 = sb[2][o];
#pragma unroll
        for (int i = 0; i < ND; i++) {
            y0 = fmaf(xr[i], sW[0][o * ND + i], y0);
            y1 = fmaf(xr[i], sW[1][o * ND + i], y1);
            y2 = fmaf(xr[i], sW[2][o * ND + i], y2);
        }
        y0 = tf32r(y0 * qsc);
        y1 = tf32r(y1);
        y2 = tf32r(y2);
        if (d < 4) {
            g_Qf[src][b][h][qt][qg * 4 + d][half] = y0;
        } else {
            g_Qf[src][b][h][qt][qg * 4][2 + half] = y0;
            g_Qf[src][b][h][qt][qg * 4 + 1][2 + half] = 0.f;
            g_Qf[src][b][h][qt][qg * 4 + 2][2 + half] = 0.f;
            g_Qf[src][b][h][qt][qg * 4 + 3][2 + half] = 0.f;
        }
        if (cj >= 0) {
            if (d < 4) {
                g_Kf[src][b][h][ch][w * 4 + d][0] = y1;
            } else {
                g_Kf[src][b][h][ch][w * 4][1] = y1;
                g_Kf[src][b][h][ch][w * 4 + 1][1] = 0.f;
                g_Kf[src][b][h][ch][w * 4 + 2][1] = 0.f;
                g_Kf[src][b][h][ch][w * 4 + 3][1] = 0.f;
            }
            g_Vf[src][b][h][ch][d * 4 + vr][vp] = y2;
            if (d == 4) {       // ones col (n=5) + zero cols (n=6,7)
                g_Vf[src][b][h][ch][20 + vr][vp] = 1.0f;
                g_Vf[src][b][h][ch][24 + vr][vp] = 0.0f;
                g_Vf[src][b][h][ch][28 + vr][vp] = 0.0f;
            }
        }
    }
}

// ---------------------------------------------------------------------------
// 3) Attention: warp = (b,h,16q); all 6 pairs fused; pure-MUFU exp.
//    Score C-frag -> EX2 in place -> PV A-frag directly (V key-permuted).
// ---------------------------------------------------------------------------
#define SMMA(s0, s1, s2, s3, A, B0, B1)                                      \
    asm volatile(                                                            \
        "mma.sync.aligned.m16n8k8.row.col.f32.tf32.tf32.f32 "                \
        "{%0,%1,%2,%3}, {%4,%5,%6,%7}, {%8,%9}, {%10,%10,%10,%10};\n"        \
        : "=f"(s0), "=f"(s1), "=f"(s2), "=f"(s3)                             \
        : "r"(A[0]), "r"(A[1]), "r"(A[2]), "r"(A[3]),                        \
          "r"(B0), "r"(B1), "f"(0.f))

#define PVMMA(O, e0, e1, e2, e3, B0, B1)                                     \
    asm volatile(                                                            \
        "mma.sync.aligned.m16n8k8.row.col.f32.tf32.tf32.f32 "                \
        "{%0,%1,%2,%3}, {%4,%5,%6,%7}, {%8,%9}, {%0,%1,%2,%3};\n"            \
        : "+f"(O[0]), "+f"(O[1]), "+f"(O[2]), "+f"(O[3])                     \
        : "r"(__float_as_uint(e0)), "r"(__float_as_uint(e2)),                \
          "r"(__float_as_uint(e1)), "r"(__float_as_uint(e3)),                \
          "r"(B0), "r"(B1))

#define DO_PAIR(P, A)                                                        \
    {                                                                        \
        float s0, s1, s2, s3;                                                \
        SMMA(s0, s1, s2, s3, ua[A], kb0, kb1);                               \
        float e0 = ex2f(s0), e1 = ex2f(s1), e2 = ex2f(s2), e3 = ex2f(s3);    \
        PVMMA(o[P], e0, e1, e2, e3, vb0, vb1);                               \
    }

__global__ void __launch_bounds__(128) attn_kernel() {
    int bi  = blockIdx.x;                 // [NB][NH][32]
    int b   = bi >> 7;
    int h   = (bi >> 5) & 3;
    int qt4 = bi & 31;
    int wid  = threadIdx.x >> 5;
    int lane = threadIdx.x & 31;
    int qt   = qt4 * 4 + wid;
    int nc = (g_nk[b] + 7) >> 3;

    unsigned ua[3][4];
#pragma unroll
    for (int a = 0; a < 3; a++) {
        float4 qv = *reinterpret_cast<const float4*>(&g_Qf[a][b][h][qt][lane][0]);
        ua[a][0] = __float_as_uint(qv.x);
        ua[a][1] = __float_as_uint(qv.y);
        ua[a][2] = __float_as_uint(qv.z);
        ua[a][3] = __float_as_uint(qv.w);
    }
    const float2* K0 = reinterpret_cast<const float2*>(&g_Kf[0][b][h][0][0][0]);
    const float2* K1 = reinterpret_cast<const float2*>(&g_Kf[1][b][h][0][0][0]);
    const float2* K2 = reinterpret_cast<const float2*>(&g_Kf[2][b][h][0][0][0]);
    const float2* V0 = reinterpret_cast<const float2*>(&g_Vf[0][b][h][0][0][0]);
    const float2* V1 = reinterpret_cast<const float2*>(&g_Vf[1][b][h][0][0][0]);
    const float2* V2 = reinterpret_cast<const float2*>(&g_Vf[2][b][h][0][0][0]);

    float o[6][4];
#pragma unroll
    for (int p = 0; p < 6; p++)
#pragma unroll
        for (int i = 0; i < 4; i++) o[p][i] = 0.f;

    for (int ch = 0; ch < nc; ch++) {
        int off = ch * 32 + lane;
        {   // kv-src 0 : pairs 1 (a=1), 3 (a=2)
            float2 kv = K0[off];
            float2 vv = V0[off];
            unsigned kb0 = __float_as_uint(kv.x), kb1 = __float_as_uint(kv.y);
            unsigned vb0 = __float_as_uint(vv.x), vb1 = __float_as_uint(vv.y);
            DO_PAIR(1, 1);
            DO_PAIR(3, 2);
        }
        {   // kv-src 1 : pairs 0 (a=0), 5 (a=2)
            float2 kv = K1[off];
            float2 vv = V1[off];
            unsigned kb0 = __float_as_uint(kv.x), kb1 = __float_as_uint(kv.y);
            unsigned vb0 = __float_as_uint(vv.x), vb1 = __float_as_uint(vv.y);
            DO_PAIR(0, 0);
            DO_PAIR(5, 2);
        }
        {   // kv-src 2 : pairs 2 (a=0), 4 (a=1)
            float2 kv = K2[off];
            float2 vv = V2[off];
            unsigned kb0 = __float_as_uint(kv.x), kb1 = __float_as_uint(kv.y);
            unsigned vb0 = __float_as_uint(vv.x), vb1 = __float_as_uint(vv.y);
            DO_PAIR(2, 0);
            DO_PAIR(4, 1);
        }
    }

    // Normalize each pair (l = col 5 -> regs 1/3 of lane group t=2), sum pairs.
    int t = lane & 3;
    int g = lane >> 2;
    unsigned lsrc = (lane & ~3u) | 2u;
    float r0 = 0.f, r1 = 0.f, r2 = 0.f, r3 = 0.f;
#pragma unroll
    for (int p = 0; p < 6; p++) {
        float llo = __shfl_sync(FULLM, o[p][1], lsrc);
        float lhi = __shfl_sync(FULLM, o[p][3], lsrc);
        float ilo = 1.0f / llo;
        float ihi = 1.0f / lhi;
        r0 = fmaf(o[p][0], ilo, r0);
        r1 = fmaf(o[p][1], ilo, r1);
        r2 = fmaf(o[p][2], ihi, r2);
        r3 = fmaf(o[p][3], ihi, r3);
    }

    int q_lo = qt * 16 + g;
    int q_hi = q_lo + 8;
    int c0 = 2 * t;
    if (c0 < 4) {
        g_O[b][q_lo][h * NDK + c0]     = r0;
        g_O[b][q_lo][h * NDK + c0 + 1] = r1;
        g_O[b][q_hi][h * NDK + c0]     = r2;
        g_O[b][q_hi][h * NDK + c0 + 1] = r3;
    } else if (c0 == 4) {
        g_O[b][q_lo][h * NDK + 4] = r0;
        g_O[b][q_hi][h * NDK + 4] = r2;
    }
}

// ---------------------------------------------------------------------------
// 4) Output projection: thread = (bs, og) -> 5 outputs
// ---------------------------------------------------------------------------
__global__ void outproj_kernel(const float* __restrict__ W3,
                               const float* __restrict__ b3,
                               float* __restrict__ out) {
    __shared__ float sW[ND * ND];
    __shared__ float sb[ND];
    for (int i = threadIdx.x; i < ND * ND; i += blockDim.x) sW[i] = W3[i];
    for (int i = threadIdx.x; i < ND; i += blockDim.x) sb[i] = b3[i];
    __syncthreads();

    int idx = blockIdx.x * blockDim.x + threadIdx.x;
    if (idx >= 4 * NB * NS) return;
    int bs = idx & (NB * NS - 1);
    int og = idx >> 14;

    const float* xp = &g_O[0][0][0] + (size_t)bs * ND;
    float x[ND];
#pragma unroll
    for (int i = 0; i < ND; i++) x[i] = xp[i];
    float* op = out + (size_t)bs * ND;
#pragma unroll
    for (int d = 0; d < 5; d++) {
        int o = og * 5 + d;
        float y = sb[o];
#pragma unroll
        for (int i = 0; i < ND; i++) y = fmaf(x[i], sW[o * ND + i], y);
        op[o] = y;
    }
}

// ---------------------------------------------------------------------------
extern "C" void kernel_launch(void* const* d_in, const int* in_sizes, int n_in,
                              void* d_out, int out_size) {
    const float* q   = (const float*)d_in[0];
    const float* k   = (const float*)d_in[1];
    const float* v   = (const float*)d_in[2];
    const int*   msk = (const int*)d_in[3];
    const float* W0  = (const float*)d_in[4];
    const float* b0  = (const float*)d_in[5];
    const float* W1  = (const float*)d_in[6];
    const float* b1  = (const float*)d_in[7];
    const float* W2  = (const float*)d_in[8];
    const float* b2  = (const float*)d_in[9];
    const float* W3  = (const float*)d_in[10];
    const float* b3  = (const float*)d_in[11];
    float* out = (float*)d_out;

    compact_kernel<<<NB, 32>>>(msk);
    proj_kernel<<<(3 * NH * NB * NS + 255) / 256, 256>>>(q, k, v, W0, b0, W1, b1, W2, b2);
    attn_kernel<<<NB * NH * 32, 128>>>();
    outproj_kernel<<<(4 * NB * NS + 255) / 256, 256>>>(W3, b3, out);
}